// round 16
// baseline (speedup 1.0000x reference)
#include <cuda_runtime.h>
#include <math.h>
#include <stdint.h>

#define Nn 512
#define Dd 128
#define Df 256
#define Hh 8
#define ROWS (Nn*Nn)
#define NT 4096                   // 64-row tiles

__device__ float sc_S[Nn * Dd];
__device__ float sc_T[Nn * Dd];
__device__ float sc_qk[Nn * Hh * Dd];        // 0.25 * Wk^T q  per (n, h)
__device__ float sc_o[Nn * Dd];
__device__ float wfrag[2][16384];            // Wm_edge, We tf32 frag layout
__device__ float sc_memf[(size_t)ROWS * Dd]; // memory f32 [n][m][c] (134MB)
__device__ float sc_part[(size_t)4096 * 1040]; // split-KV partials (17MB)

// k_fused dynamic smem float offsets
#define O_A  0                    // 8192
#define O_RS 8192                 // 256
#define O_RQ 8448                 // 256
#define O_P  8704                 // 128 (bm + T)
#define O_G  8832                 // 7*128
#define SMF  9728
#define DYN  (SMF * 4)            // 38912 B

#define G_GM  (O_G + 0)
#define G_BEM (O_G + 128)
#define G_G1  (O_G + 256)
#define G_BE1 (O_G + 384)
#define G_G2  (O_G + 512)
#define G_BE2 (O_G + 640)
#define G_BEB (O_G + 768)

__device__ __forceinline__ uint32_t tf32c(float x) {
    uint32_t y; asm("cvt.rna.tf32.f32 %0, %1;" : "=r"(y) : "f"(x)); return y;
}
__device__ __forceinline__ float tf32f(float x) { return __uint_as_float(tf32c(x)); }

__device__ __forceinline__ uint32_t smem_u32(const void* p) {
    uint32_t a;
    asm("{ .reg .u64 t; cvta.to.shared.u64 t, %1; cvt.u32.u64 %0, t; }" : "=r"(a) : "l"(p));
    return a;
}
__device__ __forceinline__ void cpa16(uint32_t s, const void* g) {
    asm volatile("cp.async.cg.shared.global [%0], [%1], 16;" :: "r"(s), "l"(g));
}
#define CPC() asm volatile("cp.async.commit_group;" ::: "memory")
#define CPW(n) asm volatile("cp.async.wait_group %0;" :: "n"(n) : "memory")

__device__ __forceinline__ void mma8(float* c, const uint32_t* a, const uint32_t* b) {
    asm volatile(
        "mma.sync.aligned.m16n8k8.row.col.f32.tf32.tf32.f32 "
        "{%0,%1,%2,%3},{%4,%5,%6,%7},{%8,%9},{%0,%1,%2,%3};"
        : "+f"(c[0]), "+f"(c[1]), "+f"(c[2]), "+f"(c[3])
        : "r"(a[0]), "r"(a[1]), "r"(a[2]), "r"(a[3]), "r"(b[0]), "r"(b[1]));
}

// A-fragment float index, plane-split layout [frag][reg(4)][qx(32)]
__device__ __forceinline__ int AFR2(int r, int c) {
    int kb = c >> 3;
    int frag = (r >> 4) * 16 + kb;
    int reg = ((r >> 3) & 1) + (((c >> 2) & 1) << 1);
    int qx = ((((r & 7) << 2) + (c & 3)) ^ ((kb & 7) << 2));
    return frag * 128 + reg * 32 + qx;
}

// 64x128x128 tile MMA: 8 warps 2(m) x 4(n), warp tile 32x32.
__device__ __forceinline__ void mma_tile(const float* sA, const float* __restrict__ gB,
                                         float c[2][4][4]) {
    int tid = threadIdx.x, w = tid >> 5, lane = tid & 31;
    int wm = w >> 2, wn = w & 3;
#pragma unroll
    for (int mt = 0; mt < 2; ++mt)
#pragma unroll
        for (int nt = 0; nt < 4; ++nt)
#pragma unroll
            for (int i = 0; i < 4; ++i) c[mt][nt][i] = 0.f;
#pragma unroll
    for (int kc = 0; kc < 16; ++kc) {
        int sw = (kc & 7) << 2;
        uint32_t a[2][4];
#pragma unroll
        for (int mt = 0; mt < 2; ++mt) {
            int base = ((wm * 2 + mt) * 16 + kc) * 128 + (lane ^ sw);
            a[mt][0] = __float_as_uint(sA[base]);
            a[mt][1] = __float_as_uint(sA[base + 32]);
            a[mt][2] = __float_as_uint(sA[base + 64]);
            a[mt][3] = __float_as_uint(sA[base + 96]);
        }
#pragma unroll
        for (int nt = 0; nt < 4; ++nt) {
            float2 bv = __ldg((const float2*)&gB[(((wn * 4 + nt) * 16 + kc) * 32 + lane) * 2]);
            uint32_t b[2] = {__float_as_uint(bv.x), __float_as_uint(bv.y)};
            mma8(c[0][nt], a[0], b);
            mma8(c[1][nt], a[1], b);
        }
    }
}

#define ROWSTATS(sv, qv, mean, rstd) do { \
    _Pragma("unroll") for (int _mt = 0; _mt < 2; ++_mt) \
    _Pragma("unroll") for (int _h = 0; _h < 2; ++_h) { \
        float _s = (sv)[_mt][_h], _q = (qv)[_mt][_h]; \
        _s += __shfl_xor_sync(0xffffffffu, _s, 1); _q += __shfl_xor_sync(0xffffffffu, _q, 1); \
        _s += __shfl_xor_sync(0xffffffffu, _s, 2); _q += __shfl_xor_sync(0xffffffffu, _q, 2); \
        (sv)[_mt][_h] = _s; (qv)[_mt][_h] = _q; } \
    if ((lane & 3) == 0) { \
        _Pragma("unroll") for (int _mt = 0; _mt < 2; ++_mt) \
        _Pragma("unroll") for (int _h = 0; _h < 2; ++_h) { \
            int _row = wm * 32 + _mt * 16 + g + _h * 8; \
            sm[O_RS + _row * 4 + wn] = (sv)[_mt][_h]; \
            sm[O_RQ + _row * 4 + wn] = (qv)[_mt][_h]; } } \
    __syncthreads(); \
    _Pragma("unroll") for (int _mt = 0; _mt < 2; ++_mt) \
    _Pragma("unroll") for (int _h = 0; _h < 2; ++_h) { \
        int _row = wm * 32 + _mt * 16 + g + _h * 8; \
        float _ts = sm[O_RS + _row * 4] + sm[O_RS + _row * 4 + 1] + sm[O_RS + _row * 4 + 2] + sm[O_RS + _row * 4 + 3]; \
        float _tq = sm[O_RQ + _row * 4] + sm[O_RQ + _row * 4 + 1] + sm[O_RQ + _row * 4 + 2] + sm[O_RQ + _row * 4 + 3]; \
        float _mn = _ts * (1.f / 128.f); \
        (mean)[_mt][_h] = _mn; \
        (rstd)[_mt][_h] = rsqrtf(fmaxf(_tq * (1.f / 128.f) - _mn * _mn, 0.f) + 1e-5f); } \
    __syncthreads(); \
} while (0)

// ---------- weight prep (Wm, We) ----------
__global__ void k_prep(const float* __restrict__ Wm, const float* __restrict__ We) {
    extern __shared__ float ws[];   // [128][129]
    const float* W = blockIdx.x == 0 ? Wm : We;
    int tid = threadIdx.x;
    for (int t = 0; t < 16; ++t) {
        int id = tid + t * 256;
        int k = id >> 5, n4 = (id & 31) << 2;
        float4 v = *(const float4*)&W[k * Dd + n4];
        ws[k * 129 + n4] = v.x; ws[k * 129 + n4 + 1] = v.y;
        ws[k * 129 + n4 + 2] = v.z; ws[k * 129 + n4 + 3] = v.w;
    }
    __syncthreads();
    float* out = wfrag[blockIdx.x];
    for (int t = 0; t < 32; ++t) {
        int id = tid + t * 256;
        int lane = id & 31, kb = (id >> 5) & 15, nb = id >> 9;
        int n = nb * 8 + (lane >> 2), k = kb * 8 + (lane & 3);
        float2 o;
        o.x = tf32f(ws[k * 129 + n]);
        o.y = tf32f(ws[(k + 4) * 129 + n]);
        *(float2*)&out[id * 2] = o;
    }
}

// ---------- S, T, qk ----------
__global__ void k_small(const float* __restrict__ node, const float* __restrict__ Wmem,
                        const float* __restrict__ Wq, const float* __restrict__ bq,
                        const float* __restrict__ Wk) {
    int n = blockIdx.x, c = threadIdx.x;
    __shared__ float ns[Dd], qs[Dd];
    ns[c] = node[n * Dd + c];
    __syncthreads();
    float s = 0.f, t = 0.f, q = 0.f;
#pragma unroll 8
    for (int k = 0; k < Dd; ++k) {
        float nv = ns[k];
        s = fmaf(nv, Wmem[(Dd + k) * Dd + c], s);
        t = fmaf(nv, Wmem[(2 * Dd + k) * Dd + c], t);
        q = fmaf(nv, Wq[k * Dd + c], q);
    }
    sc_S[n * Dd + c] = s; sc_T[n * Dd + c] = t;
    qs[c] = q + bq[c];
    __syncthreads();
    float a[8] = {0,0,0,0,0,0,0,0};
#pragma unroll
    for (int hd = 0; hd < 128; ++hd)
        a[hd >> 4] = fmaf(Wk[c * Dd + hd], qs[hd], a[hd >> 4]);
#pragma unroll
    for (int h = 0; h < 8; ++h)
        sc_qk[n * 1024 + h * 128 + c] = a[h] * 0.25f;
}

// ---------- fused tile kernel: memory (f32 out) + edge_out ----------
__global__ __launch_bounds__(256, 2) void k_fused(
    const float* __restrict__ edge,
    const float* __restrict__ bm, const float* __restrict__ gm, const float* __restrict__ bem,
    const float* __restrict__ beb, const float* __restrict__ g1, const float* __restrict__ be1,
    const float* __restrict__ g2, const float* __restrict__ be2,
    float* __restrict__ oe)
{
    extern __shared__ float sm[];
    const int tid = threadIdx.x, w = tid >> 5, lane = tid & 31;
    const int wm = w >> 2, wn = w & 3, g = lane >> 2, t2 = (lane & 3) << 1;
    const int ib = blockIdx.x >> 3, jn0 = (blockIdx.x & 7) << 6;
    const size_t r0 = (size_t)blockIdx.x * 64;

    // A <- edge (tf32 frags, plane-split layout, vector stores)
#pragma unroll
    for (int t = 0; t < 8; ++t) {
        int id = tid + t * 256;
        int r = id >> 5, c4 = (id & 31) << 2;
        float4 v = *(const float4*)&edge[(r0 + r) * Dd + c4];
        float4 o;
        o.x = tf32f(v.x); o.y = tf32f(v.y); o.z = tf32f(v.z); o.w = tf32f(v.w);
        *(float4*)&sm[O_A + AFR2(r, c4)] = o;
    }
    if (tid < Dd) {
        sm[O_P + tid]  = bm[tid] + sc_T[ib * Dd + tid];
        sm[G_GM + tid] = gm[tid];  sm[G_BEM + tid] = bem[tid];
        sm[G_G1 + tid] = g1[tid];  sm[G_BE1 + tid] = be1[tid];
        sm[G_G2 + tid] = g2[tid];  sm[G_BE2 + tid] = be2[tid];
        sm[G_BEB + tid] = beb[tid];
    }
    __syncthreads();

    float c[2][4][4];
    mma_tile(sm + O_A, wfrag[0], c);        // memory GEMM
    __syncthreads();

    // epilogue1: memory = relu(LN(c + (bm+T) + S)), rewrite A-frags (tf32)
    {
        float sv[2][2] = {{0,0},{0,0}}, qv[2][2] = {{0,0},{0,0}};
#pragma unroll
        for (int mt = 0; mt < 2; ++mt) {
            int rA = wm * 32 + mt * 16 + g;
#pragma unroll
            for (int nt = 0; nt < 4; ++nt) {
                int col = wn * 32 + nt * 8 + t2;
                float p0 = sm[O_P + col], p1 = sm[O_P + col + 1];
                float2 s0 = *(const float2*)&sc_S[(jn0 + rA) * Dd + col];
                float2 s1 = *(const float2*)&sc_S[(jn0 + rA + 8) * Dd + col];
                c[mt][nt][0] += p0 + s0.x; c[mt][nt][1] += p1 + s0.y;
                c[mt][nt][2] += p0 + s1.x; c[mt][nt][3] += p1 + s1.y;
                sv[mt][0] += c[mt][nt][0] + c[mt][nt][1];
                qv[mt][0] += c[mt][nt][0]*c[mt][nt][0] + c[mt][nt][1]*c[mt][nt][1];
                sv[mt][1] += c[mt][nt][2] + c[mt][nt][3];
                qv[mt][1] += c[mt][nt][2]*c[mt][nt][2] + c[mt][nt][3]*c[mt][nt][3];
            }
        }
        float mean[2][2], rstd[2][2];
        ROWSTATS(sv, qv, mean, rstd);
#pragma unroll
        for (int mt = 0; mt < 2; ++mt) {
            int rA = wm * 32 + mt * 16 + g;
#pragma unroll
            for (int nt = 0; nt < 4; ++nt) {
                int col = wn * 32 + nt * 8 + t2;
                float ga0 = sm[G_GM + col], ga1 = sm[G_GM + col + 1];
                float bb0 = sm[G_BEM + col], bb1 = sm[G_BEM + col + 1];
                *(float2*)&sm[O_A + AFR2(rA, col)] = make_float2(
                    tf32f(fmaxf((c[mt][nt][0]-mean[mt][0])*rstd[mt][0]*ga0+bb0, 0.f)),
                    tf32f(fmaxf((c[mt][nt][1]-mean[mt][0])*rstd[mt][0]*ga1+bb1, 0.f)));
                *(float2*)&sm[O_A + AFR2(rA + 8, col)] = make_float2(
                    tf32f(fmaxf((c[mt][nt][2]-mean[mt][1])*rstd[mt][1]*ga0+bb0, 0.f)),
                    tf32f(fmaxf((c[mt][nt][3]-mean[mt][1])*rstd[mt][1]*ga1+bb1, 0.f)));
            }
        }
    }
    __syncthreads();

    mma_tile(sm + O_A, wfrag[1], c);        // edge GEMM

    // write memory f32 [jn][ib][c], coalesced float4
#pragma unroll
    for (int t = 0; t < 8; ++t) {
        int id4 = tid + t * 256;
        int r = id4 >> 5, c4 = (id4 & 31) << 2;
        float4 o = *(const float4*)&sm[O_A + AFR2(r, c4)];
        *(float4*)&sc_memf[((size_t)(jn0 + r) * Nn + ib) * Dd + c4] = o;
    }

    // epilogue2: out_edge = LN2(edge + relu(LN1(c + beb)))
    {
        float sv[2][2] = {{0,0},{0,0}}, qv[2][2] = {{0,0},{0,0}};
#pragma unroll
        for (int mt = 0; mt < 2; ++mt)
#pragma unroll
            for (int nt = 0; nt < 4; ++nt) {
                int col = wn * 32 + nt * 8 + t2;
                float b0 = sm[G_BEB + col], b1 = sm[G_BEB + col + 1];
                c[mt][nt][0] += b0; c[mt][nt][1] += b1;
                c[mt][nt][2] += b0; c[mt][nt][3] += b1;
                sv[mt][0] += c[mt][nt][0] + c[mt][nt][1];
                qv[mt][0] += c[mt][nt][0]*c[mt][nt][0] + c[mt][nt][1]*c[mt][nt][1];
                sv[mt][1] += c[mt][nt][2] + c[mt][nt][3];
                qv[mt][1] += c[mt][nt][2]*c[mt][nt][2] + c[mt][nt][3]*c[mt][nt][3];
            }
        float mean[2][2], rstd[2][2];
        ROWSTATS(sv, qv, mean, rstd);
        float sv2[2][2] = {{0,0},{0,0}}, qv2[2][2] = {{0,0},{0,0}};
#pragma unroll
        for (int mt = 0; mt < 2; ++mt) {
            int rA = wm * 32 + mt * 16 + g;
#pragma unroll
            for (int nt = 0; nt < 4; ++nt) {
                int col = wn * 32 + nt * 8 + t2;
                float ga0 = sm[G_G1 + col], ga1 = sm[G_G1 + col + 1];
                float bb0 = sm[G_BE1 + col], bb1 = sm[G_BE1 + col + 1];
                float2 e0 = *(const float2*)&edge[(r0 + rA) * Dd + col];
                float2 e1 = *(const float2*)&edge[(r0 + rA + 8) * Dd + col];
                float w00 = fmaxf((c[mt][nt][0]-mean[mt][0])*rstd[mt][0]*ga0+bb0, 0.f) + e0.x;
                float w01 = fmaxf((c[mt][nt][1]-mean[mt][0])*rstd[mt][0]*ga1+bb1, 0.f) + e0.y;
                float w10 = fmaxf((c[mt][nt][2]-mean[mt][1])*rstd[mt][1]*ga0+bb0, 0.f) + e1.x;
                float w11 = fmaxf((c[mt][nt][3]-mean[mt][1])*rstd[mt][1]*ga1+bb1, 0.f) + e1.y;
                c[mt][nt][0] = w00; c[mt][nt][1] = w01; c[mt][nt][2] = w10; c[mt][nt][3] = w11;
                sv2[mt][0] += w00 + w01; qv2[mt][0] += w00*w00 + w01*w01;
                sv2[mt][1] += w10 + w11; qv2[mt][1] += w10*w10 + w11*w11;
            }
        }
        ROWSTATS(sv2, qv2, mean, rstd);
#pragma unroll
        for (int mt = 0; mt < 2; ++mt) {
            int rA = wm * 32 + mt * 16 + g;
#pragma unroll
            for (int nt = 0; nt < 4; ++nt) {
                int col = wn * 32 + nt * 8 + t2;
                float ga0 = sm[G_G2 + col], ga1 = sm[G_G2 + col + 1];
                float bb0 = sm[G_BE2 + col], bb1 = sm[G_BE2 + col + 1];
                *(float2*)&oe[(r0 + rA) * Dd + col] =
                    make_float2((c[mt][nt][0]-mean[mt][0])*rstd[mt][0]*ga0+bb0,
                                (c[mt][nt][1]-mean[mt][0])*rstd[mt][0]*ga1+bb1);
                *(float2*)&oe[(r0 + rA + 8) * Dd + col] =
                    make_float2((c[mt][nt][2]-mean[mt][1])*rstd[mt][1]*ga0+bb0,
                                (c[mt][nt][3]-mean[mt][1])*rstd[mt][1]*ga1+bb1);
            }
        }
    }
}

// ---------- split-KV attention: partial kernel (one 64-key chunk per block) ----------
__global__ __launch_bounds__(256, 4) void k_attnp(const unsigned char* __restrict__ mask) {
    __shared__ float qk_s[1024];     // reused as ctx partials after scores
    __shared__ float buf[64 * 132];
    __shared__ float scs[512], ps[512];
    const int bid = blockIdx.x, n = bid >> 3, part = bid & 7;
    const int tid = threadIdx.x, w = tid >> 5, lane = tid & 31;
    const uint32_t sbuf = smem_u32(buf);

    for (int i = tid; i < 1024; i += 256) qk_s[i] = sc_qk[n * 1024 + i];

    const float* src = sc_memf + ((size_t)n * Nn + part * 64) * Dd;
#pragma unroll
    for (int t = 0; t < 8; ++t) {
        int id4 = tid + t * 256;
        int m = id4 >> 5, j = id4 & 31;
        cpa16(sbuf + ((m * 132 + j * 4) << 2), src + (size_t)id4 * 4);
    }
    CPC(); CPW(0);
    __syncthreads();

    // scores: thread -> (m = sm_, heads h0, h0+1)
    {
        const int sm_ = tid & 63, h0 = (tid >> 6) << 1;
        float a0 = 0.f, a1 = 0.f;
        const float* mr = &buf[sm_ * 132];
        const float* qa = &qk_s[h0 * 128];
        const float* qb = &qk_s[(h0 + 1) * 128];
#pragma unroll 8
        for (int j = 0; j < 32; ++j) {
            float4 m4 = *(const float4*)&mr[j * 4];
            float4 a4 = *(const float4*)&qa[j * 4];
            float4 b4 = *(const float4*)&qb[j * 4];
            a0 += m4.x*a4.x + m4.y*a4.y + m4.z*a4.z + m4.w*a4.w;
            a1 += m4.x*b4.x + m4.y*b4.y + m4.z*b4.z + m4.w*b4.w;
        }
        bool mk = mask[n * Nn + part * 64 + sm_] != 0;
        scs[h0 * 64 + sm_]       = mk ? -1e30f : a0;
        scs[(h0 + 1) * 64 + sm_] = mk ? -1e30f : a1;
    }
    __syncthreads();

    float* op = &sc_part[(size_t)bid * 1040];
    // local softmax: warp w = head w (single chunk, no online rescale)
    {
        float s0v = scs[w * 64 + lane], s1v = scs[w * 64 + lane + 32];
        float mx = fmaxf(s0v, s1v);
#pragma unroll
        for (int off = 16; off >= 1; off >>= 1)
            mx = fmaxf(mx, __shfl_xor_sync(0xffffffffu, mx, off));
        float p0 = __expf(s0v - mx), p1 = __expf(s1v - mx);
        ps[w * 64 + lane] = p0; ps[w * 64 + lane + 32] = p1;
        float cs = p0 + p1;
#pragma unroll
        for (int off = 16; off >= 1; off >>= 1)
            cs += __shfl_xor_sync(0xffffffffu, cs, off);
        if (lane == 0) { op[1024 + w] = mx; op[1032 + w] = cs; }
    }
    __syncthreads();

    // unnormalized ctx: warp = (hp = w&3 -> heads 2hp,2hp+1; mh = w>>2 -> m-half)
    {
        const int hp = w & 3, mh = w >> 2;
        float a00 = 0.f, a01 = 0.f, a02 = 0.f, a03 = 0.f;
        float a10 = 0.f, a11 = 0.f, a12 = 0.f, a13 = 0.f;
        const float* pp0 = &ps[(2 * hp) * 64 + mh * 32];
        const float* pp1 = &ps[(2 * hp + 1) * 64 + mh * 32];
        const float* bp = &buf[mh * 32 * 132 + lane * 4];
#pragma unroll 8
        for (int m = 0; m < 32; ++m) {
            float p0 = pp0[m], p1 = pp1[m];
            float4 v = *(const float4*)&bp[m * 132];
            a00 = fmaf(p0, v.x, a00); a01 = fmaf(p0, v.y, a01);
            a02 = fmaf(p0, v.z, a02); a03 = fmaf(p0, v.w, a03);
            a10 = fmaf(p1, v.x, a10); a11 = fmaf(p1, v.y, a11);
            a12 = fmaf(p1, v.z, a12); a13 = fmaf(p1, v.w, a13);
        }
        __syncthreads();   // qk_s dead; safe to reuse as partial store
        if (mh == 1) {
            float* pt = &qk_s[hp * 256 + lane * 8];
            *(float4*)&pt[0] = make_float4(a00, a01, a02, a03);
            *(float4*)&pt[4] = make_float4(a10, a11, a12, a13);
        }
        __syncthreads();
        if (mh == 0) {
            const float* pt = &qk_s[hp * 256 + lane * 8];
            float4 b0 = *(const float4*)&pt[0];
            float4 b1 = *(const float4*)&pt[4];
            *(float4*)&op[(2 * hp) * 128 + lane * 4] =
                make_float4(a00 + b0.x, a01 + b0.y, a02 + b0.z, a03 + b0.w);
            *(float4*)&op[(2 * hp + 1) * 128 + lane * 4] =
                make_float4(a10 + b1.x, a11 + b1.y, a12 + b1.z, a13 + b1.w);
        }
    }
}

// ---------- split-KV attention: combine + Wv projection ----------
__global__ __launch_bounds__(256, 4) void k_attnc(const float* __restrict__ Wv,
                                                  const float* __restrict__ bv) {
    __shared__ float ctx_s[1024];
    __shared__ float f_s[64];
    __shared__ float ginv_s[8];
    const int n = blockIdx.x, tid = threadIdx.x;
    const float* base = &sc_part[(size_t)(n * 8) * 1040];

    if (tid < 8) {
        int h = tid;
        float gmax = -1e30f;
#pragma unroll
        for (int p = 0; p < 8; ++p) gmax = fmaxf(gmax, base[(size_t)p * 1040 + 1024 + h]);
        float gsum = 0.f;
#pragma unroll
        for (int p = 0; p < 8; ++p) {
            float f = __expf(base[(size_t)p * 1040 + 1024 + h] - gmax);
            f_s[p * 8 + h] = f;
            gsum = fmaf(f, base[(size_t)p * 1040 + 1032 + h], gsum);
        }
        ginv_s[h] = 1.f / gsum;
    }
    __syncthreads();

    {
        int e0 = tid * 4, h = e0 >> 7;
        float a0 = 0.f, a1 = 0.f, a2 = 0.f, a3 = 0.f;
#pragma unroll
        for (int p = 0; p < 8; ++p) {
            float f = f_s[p * 8 + h];
            float4 v = *(const float4*)&base[(size_t)p * 1040 + e0];
            a0 = fmaf(f, v.x, a0); a1 = fmaf(f, v.y, a1);
            a2 = fmaf(f, v.z, a2); a3 = fmaf(f, v.w, a3);
        }
        float inv = ginv_s[h];
        ctx_s[e0] = a0 * inv; ctx_s[e0 + 1] = a1 * inv;
        ctx_s[e0 + 2] = a2 * inv; ctx_s[e0 + 3] = a3 * inv;
    }
    __syncthreads();

    if (tid < 128) {
        int h = tid >> 4;
        float acc = bv[tid];
#pragma unroll 8
        for (int cc = 0; cc < 128; ++cc)
            acc = fmaf(ctx_s[h * 128 + cc], Wv[cc * Dd + tid], acc);
        sc_o[n * Dd + tid] = acc;
    }
}

// ---------- final: out-proj + LN + FFN + LN ----------
__device__ __forceinline__ float bsum128(float v, float* tmp) {
    int lane = threadIdx.x & 31, wid = threadIdx.x >> 5;
#pragma unroll
    for (int off = 16; off >= 1; off >>= 1) v += __shfl_xor_sync(0xffffffffu, v, off);
    if (lane == 0) tmp[wid] = v;
    __syncthreads();
    float s = tmp[0] + tmp[1] + tmp[2] + tmp[3];
    __syncthreads();
    return s;
}
__global__ void k_final(const float* __restrict__ node,
                        const float* __restrict__ Wo, const float* __restrict__ bo,
                        const float* __restrict__ g2, const float* __restrict__ be2,
                        const float* __restrict__ W1, const float* __restrict__ b1,
                        const float* __restrict__ W2, const float* __restrict__ b2,
                        const float* __restrict__ g3, const float* __restrict__ be3,
                        float* __restrict__ out_x) {
    const int n = blockIdx.x;
    const int c = threadIdx.x;
    __shared__ float os[Dd], xs[Dd], hs[Df], tmp[4];
    os[c] = sc_o[n * Dd + c];
    __syncthreads();
    float t = bo[c];
#pragma unroll 8
    for (int k = 0; k < Dd; ++k) t = fmaf(os[k], Wo[k * Dd + c], t);
    float x = node[n * Dd + c] + t;
    float mean = bsum128(x, tmp) * (1.f / 128.f);
    float d = x - mean;
    float var = bsum128(d * d, tmp) * (1.f / 128.f);
    float xn = d * rsqrtf(var + 1e-5f) * g2[c] + be2[c];
    xs[c] = xn;
    __syncthreads();
    float h0 = b1[c], h1 = b1[c + 128];
#pragma unroll 8
    for (int k = 0; k < Dd; ++k) {
        float xv = xs[k];
        h0 = fmaf(xv, W1[k * Df + c], h0);
        h1 = fmaf(xv, W1[k * Df + c + 128], h1);
    }
    hs[c] = fmaxf(h0, 0.f);
    hs[c + 128] = fmaxf(h1, 0.f);
    __syncthreads();
    float y = b2[c];
#pragma unroll 8
    for (int f = 0; f < Df; ++f) y = fmaf(hs[f], W2[f * Dd + c], y);
    float z = xn + y;
    mean = bsum128(z, tmp) * (1.f / 128.f);
    d = z - mean;
    var = bsum128(d * d, tmp) * (1.f / 128.f);
    out_x[n * Dd + c] = d * rsqrtf(var + 1e-5f) * g3[c] + be3[c];
}

// ---------- host ----------
extern "C" void kernel_launch(void* const* d_in, const int* in_sizes, int n_in,
                              void* d_out, int out_size) {
    const float* node = (const float*)d_in[0];
    const float* edge = (const float*)d_in[1];
    const unsigned char* mask = (const unsigned char*)d_in[2];
    const float* W_mem = (const float*)d_in[3];
    const float* b_mem = (const float*)d_in[4];
    const float* g_mem = (const float*)d_in[5];
    const float* be_mem = (const float*)d_in[6];
    const float* W_e = (const float*)d_in[7];
    const float* b_e = (const float*)d_in[8];
    const float* g_e1 = (const float*)d_in[9];
    const float* be_e1 = (const float*)d_in[10];
    const float* g_e2 = (const float*)d_in[11];
    const float* be_e2 = (const float*)d_in[12];
    const float* Wq = (const float*)d_in[13];
    const float* bq = (const float*)d_in[14];
    const float* Wk = (const float*)d_in[15];
    const float* bk = (const float*)d_in[16]; (void)bk;   // cancels in softmax
    const float* Wv = (const float*)d_in[17];
    const float* bv = (const float*)d_in[18];
    const float* Wo = (const float*)d_in[19];
    const float* bo = (const float*)d_in[20];
    const float* W1 = (const float*)d_in[21];
    const float* b1 = (const float*)d_in[22];
    const float* W2 = (const float*)d_in[23];
    const float* b2 = (const float*)d_in[24];
    const float* g2 = (const float*)d_in[25];
    const float* be2 = (const float*)d_in[26];
    const float* g3 = (const float*)d_in[27];
    const float* be3 = (const float*)d_in[28];

    float* out = (float*)d_out;
    float* out_x = out;
    float* out_edge = out + Nn * Dd;

    static int init = 0;
    if (!init) {
        cudaFuncSetAttribute(k_prep, cudaFuncAttributeMaxDynamicSharedMemorySize, 128 * 129 * 4);
        cudaFuncSetAttribute(k_fused, cudaFuncAttributeMaxDynamicSharedMemorySize, DYN);
        init = 1;
    }

    k_prep<<<2, 256, 128 * 129 * 4>>>(W_mem, W_e);
    k_small<<<Nn, Dd>>>(node, W_mem, Wq, bq, Wk);
    k_fused<<<NT, 256, DYN>>>(edge, b_mem, g_mem, be_mem,
                              b_e, g_e1, be_e1, g_e2, be_e2, out_edge);
    k_attnp<<<4096, 256>>>(mask);
    k_attnc<<<Nn, 256>>>(Wv, bv);
    k_final<<<Nn, 128>>>(node, Wo, bo, g2, be2, W1, b1, W2, b2, g3, be3, out_x);
}